// round 15
// baseline (speedup 1.0000x reference)
#include <cuda_runtime.h>
#include <stdint.h>

typedef unsigned long long ull;

#define OF 28672
#define IF 8192

// table: 256 groups x 20 float2 slots (17 x-pairs + 2 neg-bias pairs + 1 pad)
__device__ __align__(16) float g_xs[256 * 40];
__device__ float g_sumred[32];

// pair table: {offA, eA, offB, eB} — field->x mapping per pair
__constant__ int c_pair[17][4] = {
    {0,-10, 1,-13},   // P0  w0<<10
    {2,-16, 3,-19},   // P1  w0<<10
    {4,-12, 5,-15},   // P2  w0
    {7,-10, 8,-13},   // P3  w0>>11
    {9,-16, 10,-19},  // P4  w0>>11
    {6,-18, 14,-20},  // P5  w0 / w1<<10
    {10,-8, 11,-11},  // P6  w1<<10
    {12,-14, 13,-17}, // P7  w1<<10
    {15,-13, 16,-16}, // P8  w1
    {18,-11, 19,-14}, // P9  w1>>11
    {20,-17, 21,-20}, // P10 w1>>11
    {17,-19, 31,-18}, // P11 w1 / w2>>11
    {21,-9, 22,-12},  // P12 w2<<10
    {23,-15, 24,-18}, // P13 w2<<10
    {25,-11, 26,-14}, // P14 w2
    {27,-17, 28,-20}, // P15 w2
    {29,-12, 30,-15}, // P16 w2>>11
};

__device__ __forceinline__ float pw2(int e) {
    return __int_as_float((127 + e) << 23);
}

// prep: blocks 0-19 table, 20-51 sumx partials, 52-163 out=bias
__global__ void prep_kernel(const float* __restrict__ x,
                            const float* __restrict__ bias,
                            float* __restrict__ out) {
    const int b = blockIdx.x, t = threadIdx.x;
    if (b < 20) {
        int s = b * 256 + t;            // 0..5119 = 256 groups x 20 slots
        int g = s / 20, j = s - g * 20;
        float2 v = make_float2(0.f, 0.f);
        if (j < 17) {
            v.x = x[g * 32 + c_pair[j][0]] * pw2(c_pair[j][1]);
            v.y = x[g * 32 + c_pair[j][2]] * pw2(c_pair[j][3]);
        } else if (j < 19) {
            int a = j - 17;             // 0: even-K pairs, 1: odd-K pairs
            float sa = 0.f, sb = 0.f;
            for (int k = a; k < 17; k += 2) {
                sa += x[g * 32 + c_pair[k][0]] * pw2(c_pair[k][1]);
                sb += x[g * 32 + c_pair[k][2]] * pw2(c_pair[k][3]);
            }
            v.x = sa * -8388608.f;      // -2^23 * lane sums
            v.y = sb * -8388608.f;
        }
        *(float2*)(g_xs + s * 2) = v;
    } else if (b < 52) {
        __shared__ float red[256];
        int blk = b - 20;
        red[t] = x[blk * 256 + t];
        __syncthreads();
        #pragma unroll
        for (int off = 128; off; off >>= 1) {
            if (t < off) red[t] += red[t + off];
            __syncthreads();
        }
        if (t == 0) g_sumred[blk] = red[0];
    } else {
        int i = (b - 52) * 256 + t;
        if (i < OF) out[i] = bias[i];
    }
}

#define LOP3_OR(D, V, M) asm("lop3.b32 %0, %1, %2, 0x4B000000, 0xEA;" : "=r"(D) : "r"(V), "n"(M))
#define PK(D, LO, HI)    asm("mov.b64 %0, {%1, %2};" : "=l"(D) : "r"(LO), "r"(HI))
#define FMA2(A, B, C)    asm("fma.rn.f32x2 %0, %1, %2, %0;" : "+l"(A) : "l"(B), "l"(C))
#define ADD2(A, B)       asm("add.rn.f32x2 %0, %0, %1;" : "+l"(A) : "l"(B))
// shifts on the FMA pipe: <<10 = mad.lo(x,1024), >>11 = mul.hi(x, 2^21)
#define SHL10(D, S) asm("mad.lo.u32 %0, %1, 1024, 0;" : "=r"(D) : "r"(S))
#define SHR11(D, S) asm("mul.hi.u32 %0, %1, 2097152;" : "=r"(D) : "r"(S))

// one field-pair, both columns; FFMA2 lanes = two fields of one column, shared x-pair
#define PAIR(K, VAL, VAH, MA, VBL, VBH, MB, XP) do { \
    uint32_t aL_, bL_, aH_, bH_; ull mL_, mH_; \
    LOP3_OR(aL_, VAL, MA); LOP3_OR(bL_, VBL, MB); PK(mL_, aL_, bL_); \
    FMA2(accL[(K) & 1], mL_, XP); \
    LOP3_OR(aH_, VAH, MA); LOP3_OR(bH_, VBH, MB); PK(mH_, aH_, bH_); \
    FMA2(accH[(K) & 1], mH_, XP); \
} while (0)

// GEMV: grid (448, 8), 256 thr. Thread = 2 adjacent columns x 4 groups; CTA = K-eighth.
__global__ void __launch_bounds__(256, 5) gemv3_kernel(
    const uint32_t* __restrict__ qw,
    const float* __restrict__ scales,
    const float* __restrict__ zeros,
    float* __restrict__ out)
{
    __shared__ __align__(16) ull smx[32 * 20];   // 5.1 KB eighth table
    __shared__ ull part[512];
    __shared__ float s_sumx;
    const int t = threadIdx.x;
    const int q = blockIdx.y;                     // K-eighth 0..7

    {   // stage eighth table (320 float4 = 5120 B)
        const float4* src = (const float4*)g_xs + q * 320;
        float4* dst = (float4*)smx;
        dst[t] = src[t];
        if (t < 64) dst[t + 256] = src[t + 256];
    }
    if (q == 0 && t < 32) {
        float s = g_sumred[t];
        #pragma unroll
        for (int o = 16; o; o >>= 1) s += __shfl_xor_sync(~0u, s, o);
        if (t == 0) s_sumx = s;
    }
    __syncthreads();

    const int lane = t & 31, sl = t >> 5;
    const uint2* p = (const uint2*)(qw + (size_t)(3 * (q * 32 + sl * 4)) * OF
                                       + blockIdx.x * 64) + lane;
    const ulonglong2* xq = (const ulonglong2*)(smx + sl * 4 * 20);

    ull accL[2] = {0, 0}, accH[2] = {0, 0};
    uint2 w0 = p[0], w1 = p[OF / 2], w2 = p[OF];

    #pragma unroll 1
    for (int g = 0; g < 4; g++) {
        p += 3 * (OF / 2);
        uint2 n0 = make_uint2(0u, 0u), n1 = n0, n2 = n0;
        if (g < 3) { n0 = p[0]; n1 = p[OF / 2]; n2 = p[OF]; }

        ulonglong2 c0 = xq[0], c1 = xq[1], c2 = xq[2];
        uint32_t vax, vay, vcx, vcy;
        SHL10(vax, w0.x); SHL10(vay, w0.y);
        PAIR(0, vax, vay, 7 << 10, vax, vay, 7 << 13, c0.x);
        PAIR(1, vax, vay, 7 << 16, vax, vay, 7 << 19, c0.y);
        ulonglong2 c3 = xq[3];
        PAIR(2, w0.x, w0.y, 7 << 12, w0.x, w0.y, 7 << 15, c1.x);
        SHR11(vcx, w0.x); SHR11(vcy, w0.y);
        PAIR(3, vcx, vcy, 7 << 10, vcx, vcy, 7 << 13, c1.y);
        ulonglong2 c4 = xq[4];
        PAIR(4, vcx, vcy, 7 << 16, vcx, vcy, 3 << 19, c2.x);
        uint32_t uax, uay, ucx, ucy;
        SHL10(uax, w1.x); SHL10(uay, w1.y);
        PAIR(5, w0.x, w0.y, 7 << 18, uax, uay, 7 << 20, c2.y);
        ulonglong2 c5 = xq[5];
        PAIR(6, uax, uay, 1 << 10, uax, uay, 7 << 11, c3.x);
        PAIR(7, uax, uay, 7 << 14, uax, uay, 7 << 17, c3.y);
        ulonglong2 c6 = xq[6];
        PAIR(8, w1.x, w1.y, 7 << 13, w1.x, w1.y, 7 << 16, c4.x);
        SHR11(ucx, w1.x); SHR11(ucy, w1.y);
        PAIR(9, ucx, ucy, 7 << 11, ucx, ucy, 7 << 14, c4.y);
        ulonglong2 c7 = xq[7];
        PAIR(10, ucx, ucy, 7 << 17, ucx, ucy, 1 << 20, c5.x);
        uint32_t tax, tay, tcx, tcy;
        SHL10(tax, w2.x); SHL10(tay, w2.y);
        PAIR(12, tax, tay, 3 << 10, tax, tay, 7 << 12, c6.x);
        ulonglong2 c8 = xq[8];
        PAIR(13, tax, tay, 7 << 15, tax, tay, 7 << 18, c6.y);
        PAIR(14, w2.x, w2.y, 7 << 11, w2.x, w2.y, 7 << 14, c7.x);
        ulonglong2 c9 = xq[9];
        PAIR(15, w2.x, w2.y, 7 << 17, w2.x, w2.y, 7 << 20, c7.y);
        SHR11(tcx, w2.x); SHR11(tcy, w2.y);
        PAIR(16, tcx, tcy, 7 << 12, tcx, tcy, 7 << 15, c8.x);
        PAIR(11, w1.x, w1.y, 7 << 19, tcx, tcy, 7 << 18, c5.y);

        // contamination cancel (even-K pairs -> acc[0], odd-K -> acc[1])
        ADD2(accL[0], c8.y); ADD2(accH[0], c8.y);
        ADD2(accL[1], c9.x); ADD2(accH[1], c9.x);

        xq += 10;
        w0 = n0; w1 = n1; w2 = n2;
    }

    ADD2(accL[0], accL[1]);
    ADD2(accH[0], accH[1]);
    part[t * 2]     = accL[0];
    part[t * 2 + 1] = accH[0];
    __syncthreads();

    if (t < 64) {
        float dot = 0.f;
        #pragma unroll
        for (int s2 = 0; s2 < 8; s2++) {
            ull v = part[(s2 * 32 + (t >> 1)) * 2 + (t & 1)];
            float2 f = *(float2*)&v;
            dot += f.x + f.y;
        }
        const int c = blockIdx.x * 64 + t;
        float val = scales[c] * dot;
        if (q == 0) val = fmaf(-zeros[c], s_sumx, val);
        atomicAdd(out + c, val);
    }
}

extern "C" void kernel_launch(void* const* d_in, const int* in_sizes, int n_in,
                              void* d_out, int out_size) {
    const float*    x      = (const float*)d_in[0];
    const uint32_t* qw     = (const uint32_t*)d_in[1];
    const float*    scales = (const float*)d_in[2];
    const float*    zeros  = (const float*)d_in[3];
    const float*    bias   = (const float*)d_in[4];
    float*          out    = (float*)d_out;

    prep_kernel<<<164, 256>>>(x, bias, out);
    gemv3_kernel<<<dim3(OF / 64, 8), 256>>>(qw, scales, zeros, out);
}

// round 16
// speedup vs baseline: 1.0117x; 1.0117x over previous
#include <cuda_runtime.h>
#include <stdint.h>

typedef unsigned long long ull;

#define OF 28672
#define IF 8192

// table: 256 groups x 20 float2 slots (17 x-pairs + 2 neg-bias pairs + 1 pad)
__device__ __align__(16) float g_xs[256 * 40];
__device__ float g_sumred[32];

// pair table: {offA, eA, offB, eB} — field->x mapping per pair
__constant__ int c_pair[17][4] = {
    {0,-10, 1,-13},   // P0  w0<<10
    {2,-16, 3,-19},   // P1  w0<<10
    {4,-12, 5,-15},   // P2  w0
    {7,-10, 8,-13},   // P3  w0>>11
    {9,-16, 10,-19},  // P4  w0>>11
    {6,-18, 14,-20},  // P5  w0 / w1<<10
    {10,-8, 11,-11},  // P6  w1<<10
    {12,-14, 13,-17}, // P7  w1<<10
    {15,-13, 16,-16}, // P8  w1
    {18,-11, 19,-14}, // P9  w1>>11
    {20,-17, 21,-20}, // P10 w1>>11
    {17,-19, 31,-18}, // P11 w1 / w2>>11
    {21,-9, 22,-12},  // P12 w2<<10
    {23,-15, 24,-18}, // P13 w2<<10
    {25,-11, 26,-14}, // P14 w2
    {27,-17, 28,-20}, // P15 w2
    {29,-12, 30,-15}, // P16 w2>>11
};

__device__ __forceinline__ float pw2(int e) {
    return __int_as_float((127 + e) << 23);
}

// prep: blocks 0-19 table, 20-51 sumx partials, 52-79 out=bias (float4)
__global__ void prep_kernel(const float* __restrict__ x,
                            const float* __restrict__ bias,
                            float* __restrict__ out) {
    const int b = blockIdx.x, t = threadIdx.x;
    if (b < 20) {
        int s = b * 256 + t;            // 0..5119 = 256 groups x 20 slots
        int g = s / 20, j = s - g * 20;
        float2 v = make_float2(0.f, 0.f);
        if (j < 17) {
            v.x = x[g * 32 + c_pair[j][0]] * pw2(c_pair[j][1]);
            v.y = x[g * 32 + c_pair[j][2]] * pw2(c_pair[j][3]);
        } else if (j < 19) {
            int a = j - 17;             // 0: even-K pairs, 1: odd-K pairs
            float sa = 0.f, sb = 0.f;
            for (int k = a; k < 17; k += 2) {
                sa += x[g * 32 + c_pair[k][0]] * pw2(c_pair[k][1]);
                sb += x[g * 32 + c_pair[k][2]] * pw2(c_pair[k][3]);
            }
            v.x = sa * -8388608.f;      // -2^23 * lane sums
            v.y = sb * -8388608.f;
        }
        *(float2*)(g_xs + s * 2) = v;
    } else if (b < 52) {
        __shared__ float red[256];
        int blk = b - 20;
        red[t] = x[blk * 256 + t];
        __syncthreads();
        #pragma unroll
        for (int off = 128; off; off >>= 1) {
            if (t < off) red[t] += red[t + off];
            __syncthreads();
        }
        if (t == 0) g_sumred[blk] = red[0];
    } else {
        int i = (b - 52) * 256 + t;     // 7168 float4 = 28672 floats
        ((float4*)out)[i] = ((const float4*)bias)[i];
    }
}

#define LOP3_OR(D, V, M) asm("lop3.b32 %0, %1, %2, 0x4B000000, 0xEA;" : "=r"(D) : "r"(V), "n"(M))
#define PK(D, LO, HI)    asm("mov.b64 %0, {%1, %2};" : "=l"(D) : "r"(LO), "r"(HI))
#define FMA2(A, B, C)    asm("fma.rn.f32x2 %0, %1, %2, %0;" : "+l"(A) : "l"(B), "l"(C))
#define ADD2(A, B)       asm("add.rn.f32x2 %0, %0, %1;" : "+l"(A) : "l"(B))

// one field-pair, both columns; FFMA2 lanes = two fields of one column, shared x-pair
#define PAIR(K, VAL, VAH, MA, VBL, VBH, MB, XP) do { \
    uint32_t aL_, bL_, aH_, bH_; ull mL_, mH_; \
    LOP3_OR(aL_, VAL, MA); LOP3_OR(bL_, VBL, MB); PK(mL_, aL_, bL_); \
    FMA2(accL[(K) & 1], mL_, XP); \
    LOP3_OR(aH_, VAH, MA); LOP3_OR(bH_, VBH, MB); PK(mH_, aH_, bH_); \
    FMA2(accH[(K) & 1], mH_, XP); \
} while (0)

// GEMV: grid (448, 4), 256 thr. Thread = 2 adjacent columns x 8 groups; CTA = K-quarter.
__global__ void __launch_bounds__(256, 6) gemv3_kernel(
    const uint32_t* __restrict__ qw,
    const float* __restrict__ scales,
    const float* __restrict__ zeros,
    float* __restrict__ out)
{
    __shared__ __align__(16) ull smx[64 * 20];   // 10.2 KB quarter table
    __shared__ ull part[512];
    __shared__ float s_sumx;
    const int t = threadIdx.x;
    const int q = blockIdx.y;

    {   // stage quarter table (640 float4 = 10240 B)
        const float4* src = (const float4*)g_xs + q * 640;
        float4* dst = (float4*)smx;
        dst[t] = src[t]; dst[t + 256] = src[t + 256];
        if (t < 128) dst[t + 512] = src[t + 512];
    }
    if (q == 0 && t < 32) {
        float s = g_sumred[t];
        #pragma unroll
        for (int o = 16; o; o >>= 1) s += __shfl_xor_sync(~0u, s, o);
        if (t == 0) s_sumx = s;
    }
    __syncthreads();

    const int lane = t & 31, sl = t >> 5;
    const uint2* p = (const uint2*)(qw + (size_t)(3 * (q * 64 + sl * 8)) * OF
                                       + blockIdx.x * 64) + lane;
    const ulonglong2* xq = (const ulonglong2*)(smx + sl * 8 * 20);

    ull accL[2] = {0, 0}, accH[2] = {0, 0};
    uint2 w0 = p[0], w1 = p[OF / 2], w2 = p[OF];

    #pragma unroll 1
    for (int g = 0; g < 8; g++) {
        p += 3 * (OF / 2);
        uint2 n0 = make_uint2(0u, 0u), n1 = n0, n2 = n0;
        if (g < 7) { n0 = p[0]; n1 = p[OF / 2]; n2 = p[OF]; }

        ulonglong2 c0 = xq[0], c1 = xq[1], c2 = xq[2];
        uint32_t vax = w0.x << 10, vay = w0.y << 10;
        PAIR(0, vax, vay, 7 << 10, vax, vay, 7 << 13, c0.x);
        PAIR(1, vax, vay, 7 << 16, vax, vay, 7 << 19, c0.y);
        ulonglong2 c3 = xq[3];
        PAIR(2, w0.x, w0.y, 7 << 12, w0.x, w0.y, 7 << 15, c1.x);
        uint32_t vcx = w0.x >> 11, vcy = w0.y >> 11;
        PAIR(3, vcx, vcy, 7 << 10, vcx, vcy, 7 << 13, c1.y);
        ulonglong2 c4 = xq[4];
        PAIR(4, vcx, vcy, 7 << 16, vcx, vcy, 3 << 19, c2.x);
        uint32_t uax = w1.x << 10, uay = w1.y << 10;
        PAIR(5, w0.x, w0.y, 7 << 18, uax, uay, 7 << 20, c2.y);
        ulonglong2 c5 = xq[5];
        PAIR(6, uax, uay, 1 << 10, uax, uay, 7 << 11, c3.x);
        PAIR(7, uax, uay, 7 << 14, uax, uay, 7 << 17, c3.y);
        ulonglong2 c6 = xq[6];
        PAIR(8, w1.x, w1.y, 7 << 13, w1.x, w1.y, 7 << 16, c4.x);
        uint32_t ucx = w1.x >> 11, ucy = w1.y >> 11;
        PAIR(9, ucx, ucy, 7 << 11, ucx, ucy, 7 << 14, c4.y);
        ulonglong2 c7 = xq[7];
        PAIR(10, ucx, ucy, 7 << 17, ucx, ucy, 1 << 20, c5.x);
        uint32_t tax = w2.x << 10, tay = w2.y << 10;
        PAIR(12, tax, tay, 3 << 10, tax, tay, 7 << 12, c6.x);
        ulonglong2 c8 = xq[8];
        PAIR(13, tax, tay, 7 << 15, tax, tay, 7 << 18, c6.y);
        PAIR(14, w2.x, w2.y, 7 << 11, w2.x, w2.y, 7 << 14, c7.x);
        ulonglong2 c9 = xq[9];
        PAIR(15, w2.x, w2.y, 7 << 17, w2.x, w2.y, 7 << 20, c7.y);
        uint32_t tcx = w2.x >> 11, tcy = w2.y >> 11;
        PAIR(16, tcx, tcy, 7 << 12, tcx, tcy, 7 << 15, c8.x);
        PAIR(11, w1.x, w1.y, 7 << 19, tcx, tcy, 7 << 18, c5.y);

        // contamination cancel (even-K pairs -> acc[0], odd-K -> acc[1])
        ADD2(accL[0], c8.y); ADD2(accH[0], c8.y);
        ADD2(accL[1], c9.x); ADD2(accH[1], c9.x);

        xq += 10;
        w0 = n0; w1 = n1; w2 = n2;
    }

    ADD2(accL[0], accL[1]);
    ADD2(accH[0], accH[1]);
    part[t * 2]     = accL[0];
    part[t * 2 + 1] = accH[0];
    __syncthreads();

    if (t < 64) {
        float dot = 0.f;
        #pragma unroll
        for (int s2 = 0; s2 < 8; s2++) {
            ull v = part[(s2 * 32 + (t >> 1)) * 2 + (t & 1)];
            float2 f = *(float2*)&v;
            dot += f.x + f.y;
        }
        const int c = blockIdx.x * 64 + t;
        float val = scales[c] * dot;
        if (q == 0) val = fmaf(-zeros[c], s_sumx, val);
        atomicAdd(out + c, val);
    }
}

extern "C" void kernel_launch(void* const* d_in, const int* in_sizes, int n_in,
                              void* d_out, int out_size) {
    const float*    x      = (const float*)d_in[0];
    const uint32_t* qw     = (const uint32_t*)d_in[1];
    const float*    scales = (const float*)d_in[2];
    const float*    zeros  = (const float*)d_in[3];
    const float*    bias   = (const float*)d_in[4];
    float*          out    = (float*)d_out;

    prep_kernel<<<80, 256>>>(x, bias, out);
    gemv3_kernel<<<dim3(OF / 64, 4), 256>>>(qw, scales, zeros, out);
}